// round 2
// baseline (speedup 1.0000x reference)
#include <cuda_runtime.h>
#include <cstdint>

// Problem constants (fixed by setup_inputs): B=32, C=64, n=128, m=128, P=4.
#define N_ROWS 1048576u                 // n*m*C

// zeta scratch, TRANSPOSED to (c, i*128 + j) so the scatter kernel reads it
// coalesced. 1 MB, L2-resident.
__device__ unsigned char g_zeta_t[64u * 128u * 128u];

// ---------------------------------------------------------------------------
// JAX partitionable threefry stream, key = jax.random.key(42) -> (k1,k2)=(0,42).
// Element i (64-bit flat index, here < 2^32):
//   (o0, o1) = threefry2x32((0,42), x0 = i>>32 = 0, x1 = i)
//   bits[i]  = o0 ^ o1          (convert_element_type(bits1 ^ bits2, uint32))
// ---------------------------------------------------------------------------
__device__ __forceinline__ uint32_t threefry_bits(uint32_t i) {
    const uint32_t ks0 = 0u;
    const uint32_t ks1 = 42u;
    const uint32_t ks2 = 0x1BD11BDAu ^ ks0 ^ ks1;   // 0x1BD11BF0
    uint32_t x0 = 0u + ks0;      // counter hi word + ks0
    uint32_t x1 = i  + ks1;      // counter lo word + ks1
#define TF_RND(r) { x0 += x1; x1 = __funnelshift_l(x1, x1, (r)); x1 ^= x0; }
    TF_RND(13) TF_RND(15) TF_RND(26) TF_RND(6)
    x0 += ks1; x1 += ks2 + 1u;
    TF_RND(17) TF_RND(29) TF_RND(16) TF_RND(24)
    x0 += ks2; x1 += ks0 + 2u;
    TF_RND(13) TF_RND(15) TF_RND(26) TF_RND(6)
    x0 += ks0; x1 += ks1 + 3u;
    TF_RND(17) TF_RND(29) TF_RND(16) TF_RND(24)
    x0 += ks1; x1 += ks2 + 4u;
    TF_RND(13) TF_RND(15) TF_RND(26) TF_RND(6)
    x0 += ks2; x1 += ks0 + 5u;
#undef TF_RND
    return x0 ^ x1;
}

// JAX uniform(minval=tiny, maxval=1) + gumbel, reproduced op-for-op in f32.
__device__ __forceinline__ float bits_to_gumbel(uint32_t b) {
    const float tiny = 1.17549435e-38f;            // jnp.finfo(f32).tiny
    float f = __uint_as_float((b >> 9) | 0x3f800000u) - 1.0f;  // [0,1), mult of 2^-23
    float u = fmaxf(tiny, f + tiny);               // (1 - tiny) == 1.0f exactly
    return -logf(-logf(u));
}

// Phase 1: one thread per eta row r. argmax_p( log(max(eta_p,1e-30)) + g_p ),
// first-max tiebreak (jnp.argmax). Bits for row r are elements 4r..4r+3.
__global__ void __launch_bounds__(256) sample_zeta_kernel(const float* __restrict__ etas) {
    unsigned r = blockIdx.x * 256u + threadIdx.x;
    if (r >= N_ROWS) return;

    uint32_t b0 = threefry_bits(4u * r + 0u);
    uint32_t b1 = threefry_bits(4u * r + 1u);
    uint32_t b2 = threefry_bits(4u * r + 2u);
    uint32_t b3 = threefry_bits(4u * r + 3u);

    float4 e = __ldg(((const float4*)etas) + r);
    float t0 = logf(fmaxf(e.x, 1e-30f)) + bits_to_gumbel(b0);
    float t1 = logf(fmaxf(e.y, 1e-30f)) + bits_to_gumbel(b1);
    float t2 = logf(fmaxf(e.z, 1e-30f)) + bits_to_gumbel(b2);
    float t3 = logf(fmaxf(e.w, 1e-30f)) + bits_to_gumbel(b3);

    int zi = 0; float zv = t0;
    if (t1 > zv) { zv = t1; zi = 1; }
    if (t2 > zv) { zv = t2; zi = 2; }
    if (t3 > zv) { zv = t3; zi = 3; }

    // r = (i*m + j)*C + c  ->  transposed index c*(n*m) + (i*m + j)
    g_zeta_t[(r & 63u) * 16384u + (r >> 6)] = (unsigned char)zi;
}

// Phase 2: scatter. Each thread handles (b, c, i, 4 consecutive j), writing
// 2x8 consecutive output floats (rows 2i and 2i+1), fully coalesced float4s.
__global__ void __launch_bounds__(256) scatter_kernel(const float* __restrict__ s,
                                                      float* __restrict__ out) {
    unsigned tid = blockIdx.x * 256u + threadIdx.x;   // 8,388,608 threads
    unsigned j4 = tid & 31u;
    unsigned i  = (tid >> 5) & 127u;
    unsigned c  = (tid >> 12) & 63u;
    unsigned b  = tid >> 18;

    unsigned bc = b * 64u + c;
    float4 sv = __ldg((const float4*)(s + (bc * 128u + i) * 128u + (j4 << 2)));
    uchar4 z  = *(const uchar4*)(g_zeta_t + c * 16384u + i * 128u + (j4 << 2));

    float4 r0a, r0b, r1a, r1b;
    r0a.x = (z.x == 0) ? sv.x : 0.0f;  r0a.y = (z.x == 1) ? sv.x : 0.0f;
    r0a.z = (z.y == 0) ? sv.y : 0.0f;  r0a.w = (z.y == 1) ? sv.y : 0.0f;
    r0b.x = (z.z == 0) ? sv.z : 0.0f;  r0b.y = (z.z == 1) ? sv.z : 0.0f;
    r0b.z = (z.w == 0) ? sv.w : 0.0f;  r0b.w = (z.w == 1) ? sv.w : 0.0f;
    r1a.x = (z.x == 2) ? sv.x : 0.0f;  r1a.y = (z.x == 3) ? sv.x : 0.0f;
    r1a.z = (z.y == 2) ? sv.y : 0.0f;  r1a.w = (z.y == 3) ? sv.y : 0.0f;
    r1b.x = (z.z == 2) ? sv.z : 0.0f;  r1b.y = (z.z == 3) ? sv.z : 0.0f;
    r1b.z = (z.w == 2) ? sv.w : 0.0f;  r1b.w = (z.w == 3) ? sv.w : 0.0f;

    unsigned obase = (bc * 256u + 2u * i) * 256u + (j4 << 3);
    float4* o0 = (float4*)(out + obase);
    o0[0] = r0a; o0[1] = r0b;
    float4* o1 = (float4*)(out + obase + 256u);
    o1[0] = r1a; o1[1] = r1b;
}

extern "C" void kernel_launch(void* const* d_in, const int* in_sizes, int n_in,
                              void* d_out, int out_size) {
    // s has 33,554,432 elems; etas 4,194,304. Select by size for robustness.
    const float* s;
    const float* etas;
    if (in_sizes[0] == 33554432) { s = (const float*)d_in[0]; etas = (const float*)d_in[1]; }
    else                         { s = (const float*)d_in[1]; etas = (const float*)d_in[0]; }
    float* out = (float*)d_out;

    sample_zeta_kernel<<<N_ROWS / 256u, 256>>>(etas);
    scatter_kernel<<<(32u * 64u * 128u * 32u) / 256u, 256>>>(s, out);
}

// round 3
// speedup vs baseline: 1.0086x; 1.0086x over previous
#include <cuda_runtime.h>
#include <cstdint>

// Problem constants (fixed by setup_inputs): B=32, C=64, n=128, m=128, P=4.
#define N_ROWS 1048576u                 // n*m*C

// zeta scratch, TRANSPOSED to (c, i*128 + j) so the scatter kernel reads it
// coalesced. 1 MB, L2-resident.
__device__ unsigned char g_zeta_t[64u * 128u * 128u];

// ---------------------------------------------------------------------------
// JAX partitionable threefry stream, key = jax.random.key(42) -> (k1,k2)=(0,42).
// Element i (64-bit flat index, here < 2^32):
//   (o0, o1) = threefry2x32((0,42), x0 = i>>32 = 0, x1 = i)
//   bits[i]  = o0 ^ o1          (convert_element_type(bits1 ^ bits2, uint32))
// ---------------------------------------------------------------------------
__device__ __forceinline__ uint32_t threefry_bits(uint32_t i) {
    const uint32_t ks0 = 0u;
    const uint32_t ks1 = 42u;
    const uint32_t ks2 = 0x1BD11BDAu ^ ks0 ^ ks1;   // 0x1BD11BF0
    uint32_t x0 = 0u + ks0;      // counter hi word + ks0
    uint32_t x1 = i  + ks1;      // counter lo word + ks1
#define TF_RND(r) { x0 += x1; x1 = __funnelshift_l(x1, x1, (r)); x1 ^= x0; }
    TF_RND(13) TF_RND(15) TF_RND(26) TF_RND(6)
    x0 += ks1; x1 += ks2 + 1u;
    TF_RND(17) TF_RND(29) TF_RND(16) TF_RND(24)
    x0 += ks2; x1 += ks0 + 2u;
    TF_RND(13) TF_RND(15) TF_RND(26) TF_RND(6)
    x0 += ks0; x1 += ks1 + 3u;
    TF_RND(17) TF_RND(29) TF_RND(16) TF_RND(24)
    x0 += ks1; x1 += ks2 + 4u;
    TF_RND(13) TF_RND(15) TF_RND(26) TF_RND(6)
    x0 += ks2; x1 += ks0 + 5u;
#undef TF_RND
    return x0 ^ x1;
}

// JAX uniform(minval=tiny, maxval=1) + gumbel, reproduced op-for-op in f32.
__device__ __forceinline__ float bits_to_gumbel(uint32_t b) {
    const float tiny = 1.17549435e-38f;            // jnp.finfo(f32).tiny
    float f = __uint_as_float((b >> 9) | 0x3f800000u) - 1.0f;  // [0,1), mult of 2^-23
    float u = fmaxf(tiny, f + tiny);               // (1 - tiny) == 1.0f exactly
    return -logf(-logf(u));
}

// Phase 1: one thread per eta row r. argmax_p( log(max(eta_p,1e-30)) + g_p ),
// first-max tiebreak (jnp.argmax). Bits for row r are elements 4r..4r+3.
__global__ void __launch_bounds__(256) sample_zeta_kernel(const float* __restrict__ etas) {
    unsigned r = blockIdx.x * 256u + threadIdx.x;
    if (r >= N_ROWS) return;

    uint32_t b0 = threefry_bits(4u * r + 0u);
    uint32_t b1 = threefry_bits(4u * r + 1u);
    uint32_t b2 = threefry_bits(4u * r + 2u);
    uint32_t b3 = threefry_bits(4u * r + 3u);

    float4 e = __ldg(((const float4*)etas) + r);
    float t0 = logf(fmaxf(e.x, 1e-30f)) + bits_to_gumbel(b0);
    float t1 = logf(fmaxf(e.y, 1e-30f)) + bits_to_gumbel(b1);
    float t2 = logf(fmaxf(e.z, 1e-30f)) + bits_to_gumbel(b2);
    float t3 = logf(fmaxf(e.w, 1e-30f)) + bits_to_gumbel(b3);

    int zi = 0; float zv = t0;
    if (t1 > zv) { zv = t1; zi = 1; }
    if (t2 > zv) { zv = t2; zi = 2; }
    if (t3 > zv) { zv = t3; zi = 3; }

    // r = (i*m + j)*C + c  ->  transposed index c*(n*m) + (i*m + j)
    g_zeta_t[(r & 63u) * 16384u + (r >> 6)] = (unsigned char)zi;
}

// Phase 2: scatter. Each thread handles (b, c, i, 4 consecutive j), writing
// 2x8 consecutive output floats (rows 2i and 2i+1), fully coalesced float4s.
__global__ void __launch_bounds__(256) scatter_kernel(const float* __restrict__ s,
                                                      float* __restrict__ out) {
    unsigned tid = blockIdx.x * 256u + threadIdx.x;   // 8,388,608 threads
    unsigned j4 = tid & 31u;
    unsigned i  = (tid >> 5) & 127u;
    unsigned c  = (tid >> 12) & 63u;
    unsigned b  = tid >> 18;

    unsigned bc = b * 64u + c;
    float4 sv = __ldg((const float4*)(s + (bc * 128u + i) * 128u + (j4 << 2)));
    uchar4 z  = *(const uchar4*)(g_zeta_t + c * 16384u + i * 128u + (j4 << 2));

    float4 r0a, r0b, r1a, r1b;
    r0a.x = (z.x == 0) ? sv.x : 0.0f;  r0a.y = (z.x == 1) ? sv.x : 0.0f;
    r0a.z = (z.y == 0) ? sv.y : 0.0f;  r0a.w = (z.y == 1) ? sv.y : 0.0f;
    r0b.x = (z.z == 0) ? sv.z : 0.0f;  r0b.y = (z.z == 1) ? sv.z : 0.0f;
    r0b.z = (z.w == 0) ? sv.w : 0.0f;  r0b.w = (z.w == 1) ? sv.w : 0.0f;
    r1a.x = (z.x == 2) ? sv.x : 0.0f;  r1a.y = (z.x == 3) ? sv.x : 0.0f;
    r1a.z = (z.y == 2) ? sv.y : 0.0f;  r1a.w = (z.y == 3) ? sv.y : 0.0f;
    r1b.x = (z.z == 2) ? sv.z : 0.0f;  r1b.y = (z.z == 3) ? sv.z : 0.0f;
    r1b.z = (z.w == 2) ? sv.w : 0.0f;  r1b.w = (z.w == 3) ? sv.w : 0.0f;

    unsigned obase = (bc * 256u + 2u * i) * 256u + (j4 << 3);
    float4* o0 = (float4*)(out + obase);
    o0[0] = r0a; o0[1] = r0b;
    float4* o1 = (float4*)(out + obase + 256u);
    o1[0] = r1a; o1[1] = r1b;
}

extern "C" void kernel_launch(void* const* d_in, const int* in_sizes, int n_in,
                              void* d_out, int out_size) {
    // s has 33,554,432 elems; etas 4,194,304. Select by size for robustness.
    const float* s;
    const float* etas;
    if (in_sizes[0] == 33554432) { s = (const float*)d_in[0]; etas = (const float*)d_in[1]; }
    else                         { s = (const float*)d_in[1]; etas = (const float*)d_in[0]; }
    float* out = (float*)d_out;

    sample_zeta_kernel<<<N_ROWS / 256u, 256>>>(etas);
    scatter_kernel<<<(32u * 64u * 128u * 32u) / 256u, 256>>>(s, out);
}

// round 4
// speedup vs baseline: 1.0112x; 1.0025x over previous
#include <cuda_runtime.h>
#include <cstdint>

// Problem constants (fixed by setup_inputs): B=32, C=64, n=128, m=128, P=4.
#define N_ROWS 1048576u                 // n*m*C

// zeta scratch, TRANSPOSED to (c, i*128 + j) so the scatter kernel reads it
// coalesced. 1 MB, L2-resident.
__device__ unsigned char g_zeta_t[64u * 128u * 128u];

// ---------------------------------------------------------------------------
// JAX partitionable threefry stream, key = jax.random.key(42) -> (k1,k2)=(0,42).
// Element i (64-bit flat index, here < 2^32):
//   (o0, o1) = threefry2x32((0,42), x0 = i>>32 = 0, x1 = i)
//   bits[i]  = o0 ^ o1          (convert_element_type(bits1 ^ bits2, uint32))
// ---------------------------------------------------------------------------
__device__ __forceinline__ uint32_t threefry_bits(uint32_t i) {
    const uint32_t ks0 = 0u;
    const uint32_t ks1 = 42u;
    const uint32_t ks2 = 0x1BD11BDAu ^ ks0 ^ ks1;   // 0x1BD11BF0
    uint32_t x0 = 0u + ks0;      // counter hi word + ks0
    uint32_t x1 = i  + ks1;      // counter lo word + ks1
#define TF_RND(r) { x0 += x1; x1 = __funnelshift_l(x1, x1, (r)); x1 ^= x0; }
    TF_RND(13) TF_RND(15) TF_RND(26) TF_RND(6)
    x0 += ks1; x1 += ks2 + 1u;
    TF_RND(17) TF_RND(29) TF_RND(16) TF_RND(24)
    x0 += ks2; x1 += ks0 + 2u;
    TF_RND(13) TF_RND(15) TF_RND(26) TF_RND(6)
    x0 += ks0; x1 += ks1 + 3u;
    TF_RND(17) TF_RND(29) TF_RND(16) TF_RND(24)
    x0 += ks1; x1 += ks2 + 4u;
    TF_RND(13) TF_RND(15) TF_RND(26) TF_RND(6)
    x0 += ks2; x1 += ks0 + 5u;
#undef TF_RND
    return x0 ^ x1;
}

// JAX uniform(minval=tiny, maxval=1) + gumbel, reproduced op-for-op in f32.
__device__ __forceinline__ float bits_to_gumbel(uint32_t b) {
    const float tiny = 1.17549435e-38f;            // jnp.finfo(f32).tiny
    float f = __uint_as_float((b >> 9) | 0x3f800000u) - 1.0f;  // [0,1), mult of 2^-23
    float u = fmaxf(tiny, f + tiny);               // (1 - tiny) == 1.0f exactly
    return -logf(-logf(u));
}

// Phase 1: one thread per eta row r. argmax_p( log(max(eta_p,1e-30)) + g_p ),
// first-max tiebreak (jnp.argmax). Bits for row r are elements 4r..4r+3.
__global__ void __launch_bounds__(256) sample_zeta_kernel(const float* __restrict__ etas) {
    unsigned r = blockIdx.x * 256u + threadIdx.x;
    if (r >= N_ROWS) return;

    uint32_t b0 = threefry_bits(4u * r + 0u);
    uint32_t b1 = threefry_bits(4u * r + 1u);
    uint32_t b2 = threefry_bits(4u * r + 2u);
    uint32_t b3 = threefry_bits(4u * r + 3u);

    float4 e = __ldg(((const float4*)etas) + r);
    float t0 = logf(fmaxf(e.x, 1e-30f)) + bits_to_gumbel(b0);
    float t1 = logf(fmaxf(e.y, 1e-30f)) + bits_to_gumbel(b1);
    float t2 = logf(fmaxf(e.z, 1e-30f)) + bits_to_gumbel(b2);
    float t3 = logf(fmaxf(e.w, 1e-30f)) + bits_to_gumbel(b3);

    int zi = 0; float zv = t0;
    if (t1 > zv) { zv = t1; zi = 1; }
    if (t2 > zv) { zv = t2; zi = 2; }
    if (t3 > zv) { zv = t3; zi = 3; }

    // r = (i*m + j)*C + c  ->  transposed index c*(n*m) + (i*m + j)
    g_zeta_t[(r & 63u) * 16384u + (r >> 6)] = (unsigned char)zi;
}

// Phase 2: scatter. Each thread handles (b, c, i, 4 consecutive j), writing
// 2x8 consecutive output floats (rows 2i and 2i+1), fully coalesced float4s.
__global__ void __launch_bounds__(256) scatter_kernel(const float* __restrict__ s,
                                                      float* __restrict__ out) {
    unsigned tid = blockIdx.x * 256u + threadIdx.x;   // 8,388,608 threads
    unsigned j4 = tid & 31u;
    unsigned i  = (tid >> 5) & 127u;
    unsigned c  = (tid >> 12) & 63u;
    unsigned b  = tid >> 18;

    unsigned bc = b * 64u + c;
    float4 sv = __ldg((const float4*)(s + (bc * 128u + i) * 128u + (j4 << 2)));
    uchar4 z  = *(const uchar4*)(g_zeta_t + c * 16384u + i * 128u + (j4 << 2));

    float4 r0a, r0b, r1a, r1b;
    r0a.x = (z.x == 0) ? sv.x : 0.0f;  r0a.y = (z.x == 1) ? sv.x : 0.0f;
    r0a.z = (z.y == 0) ? sv.y : 0.0f;  r0a.w = (z.y == 1) ? sv.y : 0.0f;
    r0b.x = (z.z == 0) ? sv.z : 0.0f;  r0b.y = (z.z == 1) ? sv.z : 0.0f;
    r0b.z = (z.w == 0) ? sv.w : 0.0f;  r0b.w = (z.w == 1) ? sv.w : 0.0f;
    r1a.x = (z.x == 2) ? sv.x : 0.0f;  r1a.y = (z.x == 3) ? sv.x : 0.0f;
    r1a.z = (z.y == 2) ? sv.y : 0.0f;  r1a.w = (z.y == 3) ? sv.y : 0.0f;
    r1b.x = (z.z == 2) ? sv.z : 0.0f;  r1b.y = (z.z == 3) ? sv.z : 0.0f;
    r1b.z = (z.w == 2) ? sv.w : 0.0f;  r1b.w = (z.w == 3) ? sv.w : 0.0f;

    unsigned obase = (bc * 256u + 2u * i) * 256u + (j4 << 3);
    float4* o0 = (float4*)(out + obase);
    o0[0] = r0a; o0[1] = r0b;
    float4* o1 = (float4*)(out + obase + 256u);
    o1[0] = r1a; o1[1] = r1b;
}

extern "C" void kernel_launch(void* const* d_in, const int* in_sizes, int n_in,
                              void* d_out, int out_size) {
    // s has 33,554,432 elems; etas 4,194,304. Select by size for robustness.
    const float* s;
    const float* etas;
    if (in_sizes[0] == 33554432) { s = (const float*)d_in[0]; etas = (const float*)d_in[1]; }
    else                         { s = (const float*)d_in[1]; etas = (const float*)d_in[0]; }
    float* out = (float*)d_out;

    sample_zeta_kernel<<<N_ROWS / 256u, 256>>>(etas);
    scatter_kernel<<<(32u * 64u * 128u * 32u) / 256u, 256>>>(s, out);
}

// round 5
// speedup vs baseline: 1.1629x; 1.1501x over previous
#include <cuda_runtime.h>
#include <cstdint>

// Problem constants (fixed by setup_inputs): B=32, C=64, n=128, m=128, P=4.

// ---------------------------------------------------------------------------
// JAX partitionable threefry stream, key = jax.random.key(42) -> (k1,k2)=(0,42).
// Element i: (o0,o1) = threefry2x32((0,42), (i>>32, i&0xffffffff)) ; bits = o0^o1
// ---------------------------------------------------------------------------
__device__ __forceinline__ uint32_t threefry_bits(uint32_t i) {
    const uint32_t ks0 = 0u;
    const uint32_t ks1 = 42u;
    const uint32_t ks2 = 0x1BD11BDAu ^ ks0 ^ ks1;   // 0x1BD11BF0
    uint32_t x0 = 0u + ks0;      // counter hi word + ks0
    uint32_t x1 = i  + ks1;      // counter lo word + ks1
#define TF_RND(r) { x0 += x1; x1 = __funnelshift_l(x1, x1, (r)); x1 ^= x0; }
    TF_RND(13) TF_RND(15) TF_RND(26) TF_RND(6)
    x0 += ks1; x1 += ks2 + 1u;
    TF_RND(17) TF_RND(29) TF_RND(16) TF_RND(24)
    x0 += ks2; x1 += ks0 + 2u;
    TF_RND(13) TF_RND(15) TF_RND(26) TF_RND(6)
    x0 += ks0; x1 += ks1 + 3u;
    TF_RND(17) TF_RND(29) TF_RND(16) TF_RND(24)
    x0 += ks1; x1 += ks2 + 4u;
    TF_RND(13) TF_RND(15) TF_RND(26) TF_RND(6)
    x0 += ks2; x1 += ks0 + 5u;
#undef TF_RND
    return x0 ^ x1;
}

// JAX uniform(minval=tiny, maxval=1) + gumbel, reproduced op-for-op in f32.
__device__ __forceinline__ float bits_to_gumbel(uint32_t b) {
    const float tiny = 1.17549435e-38f;            // jnp.finfo(f32).tiny
    float f = __uint_as_float((b >> 9) | 0x3f800000u) - 1.0f;  // [0,1)
    float u = fmaxf(tiny, f + tiny);               // (1 - tiny) == 1.0f exactly
    return -logf(-logf(u));
}

// ---------------------------------------------------------------------------
// Fused kernel. One block per (c, i) tile:
//   stage 1: 256 threads compute the 512 gumbel-perturbed scores for the
//            tile's 128 eta rows (2 each) into smem, argmax -> zeta[128].
//   stage 2: stream all 32 batch slices: read s[b,c,i,0:128], scatter into
//            out rows 2i, 2i+1 with fully-coalesced float4 stores.
// Threefry/log work is overlapped with other blocks' memory traffic.
// ---------------------------------------------------------------------------
__global__ void __launch_bounds__(256) fused_unpool_kernel(
        const float* __restrict__ etas,
        const float* __restrict__ s,
        float* __restrict__ out) {
    __shared__ float vals[128][5];                 // pad 5: conflict-free argmax
    __shared__ __align__(4) unsigned char zsm[128];

    const unsigned c = blockIdx.x >> 7;            // 0..63
    const unsigned i = blockIdx.x & 127u;          // 0..127
    const unsigned t = threadIdx.x;

    // ---- stage 1: sample zeta for the 128 rows r = (i*128+j)*64 + c ----
#pragma unroll
    for (int h = 0; h < 2; ++h) {
        unsigned q = t + (unsigned)h * 256u;       // q = j*4 + p, q < 512
        unsigned j = q >> 2;
        unsigned p = q & 3u;
        unsigned ctr = 4u * ((i * 128u + j) * 64u + c) + p;
        uint32_t b = threefry_bits(ctr);
        float e = __ldg(etas + ctr);               // etas[r][p] == etas[4r+p]
        vals[j][p] = logf(fmaxf(e, 1e-30f)) + bits_to_gumbel(b);
    }
    __syncthreads();
    if (t < 128u) {                                // first-max argmax (jnp.argmax)
        float v0 = vals[t][0], v1 = vals[t][1], v2 = vals[t][2], v3 = vals[t][3];
        int zi = 0; float zv = v0;
        if (v1 > zv) { zv = v1; zi = 1; }
        if (v2 > zv) { zv = v2; zi = 2; }
        if (v3 > zv) { zv = v3; zi = 3; }
        zsm[t] = (unsigned char)zi;
    }
    __syncthreads();

    // ---- stage 2: scatter all 32 batch slices ----
    const unsigned j4 = t & 31u;                   // 4-j group 0..31
    const unsigned bl = t >> 5;                    // 0..7
    const uchar4 z = *(const uchar4*)&zsm[j4 << 2];

#pragma unroll
    for (unsigned bo = 0; bo < 4; ++bo) {
        const unsigned b  = bo * 8u + bl;
        const unsigned bc = b * 64u + c;

        float4 sv = __ldcs((const float4*)(s + (bc * 128u + i) * 128u + (j4 << 2)));

        float4 r0a, r0b, r1a, r1b;
        r0a.x = (z.x == 0) ? sv.x : 0.0f;  r0a.y = (z.x == 1) ? sv.x : 0.0f;
        r0a.z = (z.y == 0) ? sv.y : 0.0f;  r0a.w = (z.y == 1) ? sv.y : 0.0f;
        r0b.x = (z.z == 0) ? sv.z : 0.0f;  r0b.y = (z.z == 1) ? sv.z : 0.0f;
        r0b.z = (z.w == 0) ? sv.w : 0.0f;  r0b.w = (z.w == 1) ? sv.w : 0.0f;
        r1a.x = (z.x == 2) ? sv.x : 0.0f;  r1a.y = (z.x == 3) ? sv.x : 0.0f;
        r1a.z = (z.y == 2) ? sv.y : 0.0f;  r1a.w = (z.y == 3) ? sv.y : 0.0f;
        r1b.x = (z.z == 2) ? sv.z : 0.0f;  r1b.y = (z.z == 3) ? sv.z : 0.0f;
        r1b.z = (z.w == 2) ? sv.w : 0.0f;  r1b.w = (z.w == 3) ? sv.w : 0.0f;

        const unsigned obase = (bc * 256u + 2u * i) * 256u + (j4 << 3);
        __stcs((float4*)(out + obase),              r0a);
        __stcs((float4*)(out + obase + 4u),         r0b);
        __stcs((float4*)(out + obase + 256u),       r1a);
        __stcs((float4*)(out + obase + 260u),       r1b);
    }
}

extern "C" void kernel_launch(void* const* d_in, const int* in_sizes, int n_in,
                              void* d_out, int out_size) {
    // s has 33,554,432 elems; etas 4,194,304. Select by size for robustness.
    const float* s;
    const float* etas;
    if (in_sizes[0] == 33554432) { s = (const float*)d_in[0]; etas = (const float*)d_in[1]; }
    else                         { s = (const float*)d_in[1]; etas = (const float*)d_in[0]; }
    float* out = (float*)d_out;

    fused_unpool_kernel<<<64u * 128u, 256>>>(etas, s, out);
}

// round 6
// speedup vs baseline: 1.4142x; 1.2161x over previous
#include <cuda_runtime.h>
#include <cstdint>

// Problem constants (fixed by setup_inputs): B=32, C=64, n=128, m=128, P=4.

// ---------------------------------------------------------------------------
// JAX partitionable threefry stream, key = jax.random.key(42) -> (k1,k2)=(0,42).
// Element i: (o0,o1) = threefry2x32((0,42), (i>>32, i&0xffffffff)) ; bits = o0^o1
// ---------------------------------------------------------------------------
__device__ __forceinline__ uint32_t threefry_bits(uint32_t i) {
    const uint32_t ks0 = 0u;
    const uint32_t ks1 = 42u;
    const uint32_t ks2 = 0x1BD11BDAu ^ ks0 ^ ks1;   // 0x1BD11BF0
    uint32_t x0 = 0u + ks0;      // counter hi word + ks0
    uint32_t x1 = i  + ks1;      // counter lo word + ks1
#define TF_RND(r) { x0 += x1; x1 = __funnelshift_l(x1, x1, (r)); x1 ^= x0; }
    TF_RND(13) TF_RND(15) TF_RND(26) TF_RND(6)
    x0 += ks1; x1 += ks2 + 1u;
    TF_RND(17) TF_RND(29) TF_RND(16) TF_RND(24)
    x0 += ks2; x1 += ks0 + 2u;
    TF_RND(13) TF_RND(15) TF_RND(26) TF_RND(6)
    x0 += ks0; x1 += ks1 + 3u;
    TF_RND(17) TF_RND(29) TF_RND(16) TF_RND(24)
    x0 += ks1; x1 += ks2 + 4u;
    TF_RND(13) TF_RND(15) TF_RND(26) TF_RND(6)
    x0 += ks2; x1 += ks0 + 5u;
#undef TF_RND
    return x0 ^ x1;
}

// JAX uniform(minval=tiny, maxval=1) + gumbel, reproduced op-for-op in f32.
__device__ __forceinline__ float bits_to_gumbel(uint32_t b) {
    const float tiny = 1.17549435e-38f;            // jnp.finfo(f32).tiny
    float f = __uint_as_float((b >> 9) | 0x3f800000u) - 1.0f;  // [0,1)
    float u = fmaxf(tiny, f + tiny);               // (1 - tiny) == 1.0f exactly
    return -logf(-logf(u));
}

// 256-bit streaming store (sm_100+): one dense 32B sector per thread.
__device__ __forceinline__ void stg256_cs(float* p, float4 a, float4 b) {
    asm volatile("st.global.cs.v8.f32 [%0], {%1,%2,%3,%4,%5,%6,%7,%8};"
                 :: "l"(p),
                    "f"(a.x), "f"(a.y), "f"(a.z), "f"(a.w),
                    "f"(b.x), "f"(b.y), "f"(b.z), "f"(b.w)
                 : "memory");
}

// ---------------------------------------------------------------------------
// Fused kernel. One block per (c, i) tile:
//   stage 1: 256 threads compute the 512 gumbel-perturbed scores for the
//            tile's 128 eta rows (2 each) into smem, argmax -> zeta[128].
//   stage 2: stream all 32 batch slices: read s[b,c,i,0:128], scatter into
//            out rows 2i, 2i+1 with dense 256-bit stores (full warp store =
//            contiguous 1KB -> 100% wavefront efficiency).
// ---------------------------------------------------------------------------
__global__ void __launch_bounds__(256) fused_unpool_kernel(
        const float* __restrict__ etas,
        const float* __restrict__ s,
        float* __restrict__ out) {
    __shared__ float vals[128][5];                 // pad 5: conflict-free argmax
    __shared__ __align__(4) unsigned char zsm[128];

    const unsigned c = blockIdx.x >> 7;            // 0..63
    const unsigned i = blockIdx.x & 127u;          // 0..127
    const unsigned t = threadIdx.x;

    // ---- stage 1: sample zeta for the 128 rows r = (i*128+j)*64 + c ----
#pragma unroll
    for (int h = 0; h < 2; ++h) {
        unsigned q = t + (unsigned)h * 256u;       // q = j*4 + p, q < 512
        unsigned j = q >> 2;
        unsigned p = q & 3u;
        unsigned ctr = 4u * ((i * 128u + j) * 64u + c) + p;
        uint32_t b = threefry_bits(ctr);
        float e = __ldg(etas + ctr);               // etas[r][p] == etas[4r+p]
        vals[j][p] = logf(fmaxf(e, 1e-30f)) + bits_to_gumbel(b);
    }
    __syncthreads();
    if (t < 128u) {                                // first-max argmax (jnp.argmax)
        float v0 = vals[t][0], v1 = vals[t][1], v2 = vals[t][2], v3 = vals[t][3];
        int zi = 0; float zv = v0;
        if (v1 > zv) { zv = v1; zi = 1; }
        if (v2 > zv) { zv = v2; zi = 2; }
        if (v3 > zv) { zv = v3; zi = 3; }
        zsm[t] = (unsigned char)zi;
    }
    __syncthreads();

    // ---- stage 2: scatter all 32 batch slices ----
    const unsigned j4 = t & 31u;                   // 4-j group 0..31
    const unsigned bl = t >> 5;                    // 0..7
    const uchar4 z = *(const uchar4*)&zsm[j4 << 2];

#pragma unroll
    for (unsigned bo = 0; bo < 4; ++bo) {
        const unsigned b  = bo * 8u + bl;
        const unsigned bc = b * 64u + c;

        float4 sv = __ldcs((const float4*)(s + (bc * 128u + i) * 128u + (j4 << 2)));

        float4 r0a, r0b, r1a, r1b;
        r0a.x = (z.x == 0) ? sv.x : 0.0f;  r0a.y = (z.x == 1) ? sv.x : 0.0f;
        r0a.z = (z.y == 0) ? sv.y : 0.0f;  r0a.w = (z.y == 1) ? sv.y : 0.0f;
        r0b.x = (z.z == 0) ? sv.z : 0.0f;  r0b.y = (z.z == 1) ? sv.z : 0.0f;
        r0b.z = (z.w == 0) ? sv.w : 0.0f;  r0b.w = (z.w == 1) ? sv.w : 0.0f;
        r1a.x = (z.x == 2) ? sv.x : 0.0f;  r1a.y = (z.x == 3) ? sv.x : 0.0f;
        r1a.z = (z.y == 2) ? sv.y : 0.0f;  r1a.w = (z.y == 3) ? sv.y : 0.0f;
        r1b.x = (z.z == 2) ? sv.z : 0.0f;  r1b.y = (z.z == 3) ? sv.z : 0.0f;
        r1b.z = (z.w == 2) ? sv.w : 0.0f;  r1b.w = (z.w == 3) ? sv.w : 0.0f;

        const unsigned obase = (bc * 256u + 2u * i) * 256u + (j4 << 3);
        stg256_cs(out + obase,        r0a, r0b);   // row 2i
        stg256_cs(out + obase + 256u, r1a, r1b);   // row 2i+1
    }
}

extern "C" void kernel_launch(void* const* d_in, const int* in_sizes, int n_in,
                              void* d_out, int out_size) {
    // s has 33,554,432 elems; etas 4,194,304. Select by size for robustness.
    const float* s;
    const float* etas;
    if (in_sizes[0] == 33554432) { s = (const float*)d_in[0]; etas = (const float*)d_in[1]; }
    else                         { s = (const float*)d_in[1]; etas = (const float*)d_in[0]; }
    float* out = (float*)d_out;

    fused_unpool_kernel<<<64u * 128u, 256>>>(etas, s, out);
}

// round 7
// speedup vs baseline: 1.4383x; 1.0171x over previous
#include <cuda_runtime.h>
#include <cstdint>

// Problem constants (fixed by setup_inputs): B=32, C=64, n=128, m=128, P=4.

// ---------------------------------------------------------------------------
// JAX partitionable threefry stream, key = jax.random.key(42) -> (k1,k2)=(0,42).
// Element i: (o0,o1) = threefry2x32((0,42), (i>>32, i&0xffffffff)) ; bits = o0^o1
// ---------------------------------------------------------------------------
__device__ __forceinline__ uint32_t threefry_bits(uint32_t i) {
    const uint32_t ks0 = 0u;
    const uint32_t ks1 = 42u;
    const uint32_t ks2 = 0x1BD11BDAu ^ ks0 ^ ks1;   // 0x1BD11BF0
    uint32_t x0 = 0u + ks0;      // counter hi word + ks0
    uint32_t x1 = i  + ks1;      // counter lo word + ks1
#define TF_RND(r) { x0 += x1; x1 = __funnelshift_l(x1, x1, (r)); x1 ^= x0; }
    TF_RND(13) TF_RND(15) TF_RND(26) TF_RND(6)
    x0 += ks1; x1 += ks2 + 1u;
    TF_RND(17) TF_RND(29) TF_RND(16) TF_RND(24)
    x0 += ks2; x1 += ks0 + 2u;
    TF_RND(13) TF_RND(15) TF_RND(26) TF_RND(6)
    x0 += ks0; x1 += ks1 + 3u;
    TF_RND(17) TF_RND(29) TF_RND(16) TF_RND(24)
    x0 += ks1; x1 += ks2 + 4u;
    TF_RND(13) TF_RND(15) TF_RND(26) TF_RND(6)
    x0 += ks2; x1 += ks0 + 5u;
#undef TF_RND
    return x0 ^ x1;
}

// JAX uniform(minval=tiny, maxval=1) + gumbel, reproduced op-for-op in f32.
__device__ __forceinline__ float bits_to_gumbel(uint32_t b) {
    const float tiny = 1.17549435e-38f;            // jnp.finfo(f32).tiny
    float f = __uint_as_float((b >> 9) | 0x3f800000u) - 1.0f;  // [0,1)
    float u = fmaxf(tiny, f + tiny);               // (1 - tiny) == 1.0f exactly
    return -logf(-logf(u));
}

// 256-bit streaming store (sm_100+): one dense 32B sector per thread.
__device__ __forceinline__ void stg256_cs(float* p, float4 a, float4 b) {
    asm volatile("st.global.cs.v8.f32 [%0], {%1,%2,%3,%4,%5,%6,%7,%8};"
                 :: "l"(p),
                    "f"(a.x), "f"(a.y), "f"(a.z), "f"(a.w),
                    "f"(b.x), "f"(b.y), "f"(b.z), "f"(b.w)
                 : "memory");
}

// Scatter one s-float4 into two dense 8-float output rows and store.
__device__ __forceinline__ void scatter_store(float* out_row0, float4 sv, uchar4 z) {
    float4 r0a, r0b, r1a, r1b;
    r0a.x = (z.x == 0) ? sv.x : 0.0f;  r0a.y = (z.x == 1) ? sv.x : 0.0f;
    r0a.z = (z.y == 0) ? sv.y : 0.0f;  r0a.w = (z.y == 1) ? sv.y : 0.0f;
    r0b.x = (z.z == 0) ? sv.z : 0.0f;  r0b.y = (z.z == 1) ? sv.z : 0.0f;
    r0b.z = (z.w == 0) ? sv.w : 0.0f;  r0b.w = (z.w == 1) ? sv.w : 0.0f;
    r1a.x = (z.x == 2) ? sv.x : 0.0f;  r1a.y = (z.x == 3) ? sv.x : 0.0f;
    r1a.z = (z.y == 2) ? sv.y : 0.0f;  r1a.w = (z.y == 3) ? sv.y : 0.0f;
    r1b.x = (z.z == 2) ? sv.z : 0.0f;  r1b.y = (z.z == 3) ? sv.z : 0.0f;
    r1b.z = (z.w == 2) ? sv.w : 0.0f;  r1b.w = (z.w == 3) ? sv.w : 0.0f;
    stg256_cs(out_row0,        r0a, r0b);          // row 2i
    stg256_cs(out_row0 + 256u, r1a, r1b);          // row 2i+1
}

// ---------------------------------------------------------------------------
// Fused kernel. One block per (c, i) tile:
//   stage 1: 256 threads compute the 512 gumbel-perturbed scores for the
//            tile's 128 eta rows (2 each) into smem, argmax -> zeta[128].
//   stage 2: stream all 32 batch slices with a depth-2 load pipeline so two
//            s-loads are always in flight per warp; dense 256-bit stores.
// ---------------------------------------------------------------------------
__global__ void __launch_bounds__(256) fused_unpool_kernel(
        const float* __restrict__ etas,
        const float* __restrict__ s,
        float* __restrict__ out) {
    __shared__ float vals[128][5];                 // pad 5: conflict-free argmax
    __shared__ __align__(4) unsigned char zsm[128];

    const unsigned c = blockIdx.x >> 7;            // 0..63
    const unsigned i = blockIdx.x & 127u;          // 0..127
    const unsigned t = threadIdx.x;

    // ---- stage 1: sample zeta for the 128 rows r = (i*128+j)*64 + c ----
#pragma unroll
    for (int h = 0; h < 2; ++h) {
        unsigned q = t + (unsigned)h * 256u;       // q = j*4 + p, q < 512
        unsigned j = q >> 2;
        unsigned p = q & 3u;
        unsigned ctr = 4u * ((i * 128u + j) * 64u + c) + p;
        uint32_t b = threefry_bits(ctr);
        float e = __ldg(etas + ctr);               // etas[r][p] == etas[4r+p]
        vals[j][p] = logf(fmaxf(e, 1e-30f)) + bits_to_gumbel(b);
    }
    __syncthreads();
    if (t < 128u) {                                // first-max argmax (jnp.argmax)
        float v0 = vals[t][0], v1 = vals[t][1], v2 = vals[t][2], v3 = vals[t][3];
        int zi = 0; float zv = v0;
        if (v1 > zv) { zv = v1; zi = 1; }
        if (v2 > zv) { zv = v2; zi = 2; }
        if (v3 > zv) { zv = v3; zi = 3; }
        zsm[t] = (unsigned char)zi;
    }
    __syncthreads();

    // ---- stage 2: scatter all 32 batch slices (depth-2 load pipeline) ----
    const unsigned j4 = t & 31u;                   // 4-j group 0..31
    const unsigned bl = t >> 5;                    // 0..7
    const uchar4 z = *(const uchar4*)&zsm[j4 << 2];

    // b = bo*8 + bl, bo = 0..3. Per-bo strides: bc += 8*64 -> s += 8*64*16384,
    // out += 8*64*65536.
    const float* sp = s   + (((bl * 64u + c) * 128u + i) * 128u) + (j4 << 2);
    float*       op = out + ((bl * 64u + c) * 256u + 2u * i) * 256u + (j4 << 3);
    const unsigned S_STRIDE = 8u * 64u * 16384u;
    const unsigned O_STRIDE = 8u * 64u * 65536u;

    float4 sv0 = __ldcs((const float4*)(sp));
    float4 sv1 = __ldcs((const float4*)(sp + S_STRIDE));
    float4 sv2 = __ldcs((const float4*)(sp + 2u * S_STRIDE));
    scatter_store(op, sv0, z);
    float4 sv3 = __ldcs((const float4*)(sp + 3u * S_STRIDE));
    scatter_store(op + O_STRIDE, sv1, z);
    scatter_store(op + 2u * O_STRIDE, sv2, z);
    scatter_store(op + 3u * O_STRIDE, sv3, z);
}

extern "C" void kernel_launch(void* const* d_in, const int* in_sizes, int n_in,
                              void* d_out, int out_size) {
    // s has 33,554,432 elems; etas 4,194,304. Select by size for robustness.
    const float* s;
    const float* etas;
    if (in_sizes[0] == 33554432) { s = (const float*)d_in[0]; etas = (const float*)d_in[1]; }
    else                         { s = (const float*)d_in[1]; etas = (const float*)d_in[0]; }
    float* out = (float*)d_out;

    fused_unpool_kernel<<<64u * 128u, 256>>>(etas, s, out);
}